// round 3
// baseline (speedup 1.0000x reference)
#include <cuda_runtime.h>

// ---------------------------------------------------------------------------
// FastRx_wo_Diag: full model in fp32.
// Inputs (metadata order):
//  0 proc_codes i32 (64,32)   1 med_codes i32 (64,16)  2 emb_table f32 (3502,128)
//  3 conv_w (3,)  4 conv_b (1,)
//  5 wq (128,256) 6 wk (128,256) 7 wv (128,256) 8 wr (256,256) 9 alpha (256,) 10 beta (256,)
// 11 ehr_adj_norm (4000,4000) 12 ddi_adj_norm (4000,4000) 13 ddi_adj_raw (4000,4000)
// 14 ehr_w1 (4000,256) 15 ehr_b1 (256,) 16 ehr_w2 (256,256) 17 ehr_b2 (256,)
// 18 ddi_w1 (4000,256) 19 ddi_b1 (256,) 20 ddi_w2 (256,256) 21 ddi_b2 (256,)
// 22 inter (1,) 23 out_w1 (768,512) 24 out_b1 (512,) 25 out_w2 (512,4000) 26 out_b2 (4000,)
// Output: result (4000 f32) then batch_neg (1 f32) -> 4001 floats.
// ---------------------------------------------------------------------------

#define RCAP 128          // max nonzeros per adjacency row (mean ~41, sd ~6.3)
#define NV   64
#define VMED 4000

// ------------------------------ scratch (static device globals; no allocs) --
__device__ float g_x[NV * 128];
__device__ float g_q[NV * 256];
__device__ float g_k[NV * 256];
__device__ float g_v[NV * 256];
__device__ float g_gq[256];
__device__ float g_gk[256];
__device__ float g_feat[NV * 256];
__device__ float g_query[256];
__device__ float g_vw[NV];

__device__ float g_ellval[2][VMED * RCAP];
__device__ int   g_ellcol[2][VMED * RCAP];
__device__ int   g_elln[2][VMED];
__device__ float g_t[2][VMED * 256];
__device__ float g_dm[VMED * 256];

__device__ float g_s[VMED];
__device__ int   g_maxint;
__device__ float g_f1p[125][256];
__device__ float g_esum[125];
__device__ float g_hid[512];
__device__ float g_sp[VMED];
__device__ float g_negp[500];

// ------------------------------ helpers ------------------------------------
__device__ __forceinline__ float warp_sum(float v) {
    #pragma unroll
    for (int o = 16; o; o >>= 1) v += __shfl_xor_sync(0xffffffffu, v, o);
    return v;
}
__device__ __forceinline__ float warp_max(float v) {
    #pragma unroll
    for (int o = 16; o; o >>= 1) v = fmaxf(v, __shfl_xor_sync(0xffffffffu, v, o));
    return v;
}
// order-preserving float<->int for atomicMax (works for negatives)
__device__ __forceinline__ int f2ord(float f) {
    int i = __float_as_int(f);
    return i >= 0 ? i : (i ^ 0x7fffffff);
}
__device__ __forceinline__ float ord2f(int i) {
    return __int_as_float(i >= 0 ? i : (i ^ 0x7fffffff));
}

// ------------------------------ front: embedding mean + conv ---------------
__global__ void kfa(const int* __restrict__ pc, const float* __restrict__ emb,
                    const float* __restrict__ cw, const float* __restrict__ cb) {
    __shared__ float xm[130];
    __shared__ int cs[32];
    int v = blockIdx.x, f = threadIdx.x;          // 64 blocks x 128 threads
    if (v == 0 && f == 0) g_maxint = (int)0x80000000;   // init for fact1 softmax
    if (f < 32) cs[f] = pc[v * 32 + f];
    __syncthreads();
    float a = 0.f;
    #pragma unroll 4
    for (int k = 0; k < 32; k++) a += emb[cs[k] * 128 + f];
    xm[f + 1] = a * (1.f / 32.f);
    if (f == 0) { xm[0] = 0.f; xm[129] = 0.f; }
    __syncthreads();
    float w0 = cw[0], w1 = cw[1], w2 = cw[2], b = cb[0];
    g_x[v * 128 + f] = fmaxf(w0 * xm[f] + w1 * xm[f + 1] + w2 * xm[f + 2] + b, 0.f);
}

// ------------------------------ front: q,k,v = x @ W -----------------------
__global__ void kfb(const float* __restrict__ wq, const float* __restrict__ wk,
                    const float* __restrict__ wv) {
    __shared__ float xr[128];
    int b = blockIdx.x, v = b & 63, m = b >> 6, t = threadIdx.x;  // 192 x 256
    const float* W = (m == 0) ? wq : (m == 1) ? wk : wv;
    float* D = (m == 0) ? g_q : (m == 1) ? g_k : g_v;
    if (t < 128) xr[t] = g_x[v * 128 + t];
    __syncthreads();
    float acc = 0.f;
    #pragma unroll 8
    for (int f = 0; f < 128; f++) acc += xr[f] * W[f * 256 + t];
    D[v * 256 + t] = acc;
}

// ------------------------------ front: fastformer global vectors -----------
__global__ void kfc(const float* __restrict__ alpha, const float* __restrict__ beta) {
    __shared__ float m1[64], rd1[64], gqs[256], m2[64], rd2[64];
    const float scale = 0.0625f;                   // 256^-0.5
    int t = threadIdx.x, lane = t & 31, w = t >> 5;  // 1 block x 256
    // per-row softmax stats of q*alpha*scale
    for (int rr = 0; rr < 8; rr++) {
        int r = w * 8 + rr;
        float z[8], mx = -1e30f;
        #pragma unroll
        for (int j = 0; j < 8; j++) {
            int e = lane + j * 32;
            z[j] = g_q[r * 256 + e] * alpha[e] * scale;
            mx = fmaxf(mx, z[j]);
        }
        mx = warp_max(mx);
        float s = 0.f;
        #pragma unroll
        for (int j = 0; j < 8; j++) s += expf(z[j] - mx);
        s = warp_sum(s);
        if (lane == 0) { m1[r] = mx; rd1[r] = 1.f / s; }
    }
    __syncthreads();
    {   // gq[e] = sum_v q * softmax_e(q*alpha*scale)
        float a = alpha[t] * scale, acc = 0.f;
        for (int v = 0; v < 64; v++) {
            float q = g_q[v * 256 + t];
            acc += q * expf(q * a - m1[v]) * rd1[v];
        }
        gqs[t] = acc; g_gq[t] = acc;
    }
    __syncthreads();
    // stats for p = gq*k
    for (int rr = 0; rr < 8; rr++) {
        int r = w * 8 + rr;
        float z[8], mx = -1e30f;
        #pragma unroll
        for (int j = 0; j < 8; j++) {
            int e = lane + j * 32;
            z[j] = gqs[e] * g_k[r * 256 + e] * beta[e] * scale;
            mx = fmaxf(mx, z[j]);
        }
        mx = warp_max(mx);
        float s = 0.f;
        #pragma unroll
        for (int j = 0; j < 8; j++) s += expf(z[j] - mx);
        s = warp_sum(s);
        if (lane == 0) { m2[r] = mx; rd2[r] = 1.f / s; }
    }
    __syncthreads();
    {   // gk[e] = sum_v p * softmax_e(p*beta*scale)
        float bsc = beta[t] * scale, gq_e = gqs[t], acc = 0.f;
        for (int v = 0; v < 64; v++) {
            float p = gq_e * g_k[v * 256 + t];
            acc += p * expf(p * bsc - m2[v]) * rd2[v];
        }
        g_gk[t] = acc;
    }
}

// ------------------------------ front: feat = (gk*v)@wr + q ----------------
__global__ void kfd(const float* __restrict__ wr) {
    __shared__ float gv[256];
    int v = blockIdx.x, t = threadIdx.x;          // 64 x 256
    gv[t] = g_gk[t] * g_v[v * 256 + t];
    __syncthreads();
    float acc = g_q[v * 256 + t];
    #pragma unroll 8
    for (int e = 0; e < 256; e++) acc += gv[e] * wr[e * 256 + t];
    g_feat[v * 256 + t] = acc;
}

// ------------------------------ front: query, visit_w ----------------------
__global__ void kfe() {
    __shared__ float qy[256], s[64], mxs, rss;
    int t = threadIdx.x, lane = t & 31, w = t >> 5;  // 1 x 256
    qy[t] = g_feat[63 * 256 + t];
    g_query[t] = qy[t];
    __syncthreads();
    for (int rr = 0; rr < 8; rr++) {
        int r = w + rr * 8;
        float a = 0.f;
        if (r < 63) {
            #pragma unroll
            for (int j = 0; j < 8; j++) {
                int e = lane + j * 32;
                a += qy[e] * g_feat[r * 256 + e];
            }
        }
        a = warp_sum(a);
        if (lane == 0 && r < 63) s[r] = a;
    }
    __syncthreads();
    if (t == 0) {
        float mx = -1e30f;
        for (int i = 0; i < 63; i++) mx = fmaxf(mx, s[i]);
        float sm = 0.f;
        for (int i = 0; i < 63; i++) sm += expf(s[i] - mx);
        mxs = mx; rss = 1.f / sm;
    }
    __syncthreads();
    if (t < 63) g_vw[t] = expf(s[t] - mxs) * rss;
}

// ------------------------------ GCN stage 1: ELL build + h + t=h@w2 --------
__global__ void __launch_bounds__(256) kgcn1(
    const float* __restrict__ ehr_adj, const float* __restrict__ ddi_adj,
    const float* __restrict__ ehr_w1, const float* __restrict__ ehr_b1,
    const float* __restrict__ ehr_w2,
    const float* __restrict__ ddi_w1, const float* __restrict__ ddi_b1,
    const float* __restrict__ ddi_w2) {
    int bid = blockIdx.x;                          // 8000 x 256
    int mat = (bid >= VMED) ? 1 : 0;
    int r = bid - mat * VMED;
    const float* adj = mat ? ddi_adj : ehr_adj;
    const float* w1  = mat ? ddi_w1  : ehr_w1;
    const float* b1  = mat ? ddi_b1  : ehr_b1;
    const float* w2  = mat ? ddi_w2  : ehr_w2;

    __shared__ float val_s[RCAP];
    __shared__ int   col_s[RCAP];
    __shared__ float h_s[256];
    __shared__ int   woff[8];
    __shared__ int   nnz_s;
    __shared__ float4 part[256];

    int t = threadIdx.x, lane = t & 31, w = t >> 5;

    // --- scan 16 floats per thread (threads 0..249 cover 4000) ---
    float arr[16];
    int cnt = 0;
    const float4* rowp = (const float4*)(adj + (size_t)r * 4000);
    if (t < 250) {
        #pragma unroll
        for (int j = 0; j < 4; j++) {
            float4 q = rowp[t * 4 + j];
            arr[j * 4 + 0] = q.x; arr[j * 4 + 1] = q.y;
            arr[j * 4 + 2] = q.z; arr[j * 4 + 3] = q.w;
        }
        #pragma unroll
        for (int j = 0; j < 16; j++) cnt += (arr[j] != 0.f);
    } else {
        #pragma unroll
        for (int j = 0; j < 16; j++) arr[j] = 0.f;
    }
    // block exclusive scan (deterministic, column-ordered)
    int incl = cnt;
    #pragma unroll
    for (int o = 1; o < 32; o <<= 1) {
        int x = __shfl_up_sync(0xffffffffu, incl, o);
        if (lane >= o) incl += x;
    }
    if (lane == 31) woff[w] = incl;
    __syncthreads();
    if (t == 0) {
        int s = 0;
        #pragma unroll
        for (int i = 0; i < 8; i++) { int c = woff[i]; woff[i] = s; s += c; }
        nnz_s = (s < RCAP) ? s : RCAP;
    }
    __syncthreads();
    int pos = woff[w] + incl - cnt;
    if (t < 250) {
        #pragma unroll
        for (int j = 0; j < 16; j++) {
            float vv = arr[j];
            if (vv != 0.f) {
                if (pos < RCAP) { val_s[pos] = vv; col_s[pos] = t * 16 + j; }
                pos++;
            }
        }
    }
    __syncthreads();
    int n = nnz_s;
    for (int i = t; i < n; i += 256) {
        g_ellval[mat][r * RCAP + i] = val_s[i];
        g_ellcol[mat][r * RCAP + i] = col_s[i];
    }
    if (t == 0) g_elln[mat][r] = n;

    // --- h = relu(spmm row + b1), split over 4 nnz segments x 64 col-quads --
    int eg = (t & 63) << 2;      // column base (0..252 step 4)
    int seg = t >> 6;            // 0..3
    float4 acc = {0.f, 0.f, 0.f, 0.f};
    int i0 = (n * seg) >> 2, i1 = (n * (seg + 1)) >> 2;
    for (int i = i0; i < i1; i++) {
        float vv = val_s[i];
        const float4 wv = *(const float4*)(w1 + (size_t)col_s[i] * 256 + eg);
        acc.x += vv * wv.x; acc.y += vv * wv.y; acc.z += vv * wv.z; acc.w += vv * wv.w;
    }
    part[t] = acc;
    __syncthreads();
    if (seg == 0) {
        float4 p0 = part[t], p1 = part[t + 64], p2 = part[t + 128], p3 = part[t + 192];
        float4 bb = *(const float4*)(b1 + eg);
        float4 hh;
        hh.x = fmaxf(p0.x + p1.x + p2.x + p3.x + bb.x, 0.f);
        hh.y = fmaxf(p0.y + p1.y + p2.y + p3.y + bb.y, 0.f);
        hh.z = fmaxf(p0.z + p1.z + p2.z + p3.z + bb.z, 0.f);
        hh.w = fmaxf(p0.w + p1.w + p2.w + p3.w + bb.w, 0.f);
        *(float4*)(h_s + eg) = hh;
    }
    __syncthreads();

    // --- t_row = h @ w2, split over 4 f-segments x 64 col-quads -------------
    float4 a2 = {0.f, 0.f, 0.f, 0.f};
    int f0 = seg * 64;
    #pragma unroll 4
    for (int f = f0; f < f0 + 64; f++) {
        float hv = h_s[f];
        const float4 wv = *(const float4*)(w2 + (size_t)f * 256 + eg);
        a2.x += hv * wv.x; a2.y += hv * wv.y; a2.z += hv * wv.z; a2.w += hv * wv.w;
    }
    part[t] = a2;
    __syncthreads();
    if (seg == 0) {
        float4 p0 = part[t], p1 = part[t + 64], p2 = part[t + 128], p3 = part[t + 192];
        float4 o;
        o.x = p0.x + p1.x + p2.x + p3.x;
        o.y = p0.y + p1.y + p2.y + p3.y;
        o.z = p0.z + p1.z + p2.z + p3.z;
        o.w = p0.w + p1.w + p2.w + p3.w;
        *(float4*)(&g_t[mat][(size_t)r * 256 + eg]) = o;
    }
}

// ------------------------------ GCN stage 2: dm = spmm(t_e)+b2e - i*(...) --
__global__ void __launch_bounds__(256) kgcn2(
    const float* __restrict__ b2e, const float* __restrict__ b2d,
    const float* __restrict__ inter) {
    int r = blockIdx.x, t = threadIdx.x;           // 4000 x 256
    __shared__ float ve[RCAP]; __shared__ int ce[RCAP];
    __shared__ float vd[RCAP]; __shared__ int cd[RCAP];
    __shared__ float4 part[256];
    int ne = g_elln[0][r], nd = g_elln[1][r];
    for (int i = t; i < ne; i += 256) { ve[i] = g_ellval[0][r * RCAP + i]; ce[i] = g_ellcol[0][r * RCAP + i]; }
    for (int i = t; i < nd; i += 256) { vd[i] = g_ellval[1][r * RCAP + i]; cd[i] = g_ellcol[1][r * RCAP + i]; }
    __syncthreads();
    int eg = (t & 63) << 2, seg = t >> 6;

    float4 acc = {0.f, 0.f, 0.f, 0.f};
    for (int i = (ne * seg) >> 2; i < (ne * (seg + 1)) >> 2; i++) {
        float vv = ve[i];
        const float4 tv = *(const float4*)(&g_t[0][(size_t)ce[i] * 256 + eg]);
        acc.x += vv * tv.x; acc.y += vv * tv.y; acc.z += vv * tv.z; acc.w += vv * tv.w;
    }
    part[t] = acc;
    __syncthreads();
    float4 acce = {0.f, 0.f, 0.f, 0.f};
    if (seg == 0) {
        float4 p0 = part[t], p1 = part[t + 64], p2 = part[t + 128], p3 = part[t + 192];
        acce.x = p0.x + p1.x + p2.x + p3.x; acce.y = p0.y + p1.y + p2.y + p3.y;
        acce.z = p0.z + p1.z + p2.z + p3.z; acce.w = p0.w + p1.w + p2.w + p3.w;
    }
    __syncthreads();
    float4 a2 = {0.f, 0.f, 0.f, 0.f};
    for (int i = (nd * seg) >> 2; i < (nd * (seg + 1)) >> 2; i++) {
        float vv = vd[i];
        const float4 tv = *(const float4*)(&g_t[1][(size_t)cd[i] * 256 + eg]);
        a2.x += vv * tv.x; a2.y += vv * tv.y; a2.z += vv * tv.z; a2.w += vv * tv.w;
    }
    part[t] = a2;
    __syncthreads();
    if (seg == 0) {
        float4 p0 = part[t], p1 = part[t + 64], p2 = part[t + 128], p3 = part[t + 192];
        float4 accd;
        accd.x = p0.x + p1.x + p2.x + p3.x; accd.y = p0.y + p1.y + p2.y + p3.y;
        accd.z = p0.z + p1.z + p2.z + p3.z; accd.w = p0.w + p1.w + p2.w + p3.w;
        float iv = inter[0];
        float4 be = *(const float4*)(b2e + eg);
        float4 bd = *(const float4*)(b2d + eg);
        float4 o;
        o.x = (acce.x + be.x) - iv * (accd.x + bd.x);
        o.y = (acce.y + be.y) - iv * (accd.y + bd.y);
        o.z = (acce.z + be.z) - iv * (accd.z + bd.z);
        o.w = (acce.w + be.w) - iv * (accd.w + bd.w);
        *(float4*)(&g_dm[(size_t)r * 256 + eg]) = o;
    }
}

// ------------------------------ fact1: scores + global max -----------------
__global__ void kf1a() {
    __shared__ float qys[256];
    int t = threadIdx.x;                            // 500 x 256
    qys[t] = g_query[t];
    __syncthreads();
    int lane = t & 31, w = t >> 5;
    int r = blockIdx.x * 8 + w;
    const float4* dp = (const float4*)(g_dm + (size_t)r * 256);
    const float4* qp = (const float4*)qys;
    float a = 0.f;
    #pragma unroll 2
    for (int j = lane; j < 64; j += 32) {
        float4 d = dp[j], q = qp[j];
        a += d.x * q.x + d.y * q.y + d.z * q.z + d.w * q.w;
    }
    a = warp_sum(a);
    if (lane == 0) { g_s[r] = a; atomicMax(&g_maxint, f2ord(a)); }
}

// ------------------------------ fact1: per-block exp-weighted partials -----
__global__ void kf1b() {
    __shared__ float ev[32];
    int t = threadIdx.x, r0 = blockIdx.x * 32;      // 125 x 256
    float m = ord2f(g_maxint);
    if (t < 32) ev[t] = expf(g_s[r0 + t] - m);
    __syncthreads();
    float acc = 0.f;
    #pragma unroll 4
    for (int j = 0; j < 32; j++) acc += ev[j] * g_dm[(size_t)(r0 + j) * 256 + t];
    g_f1p[blockIdx.x][t] = acc;
    if (t == 0) {
        float s = 0.f;
        #pragma unroll
        for (int j = 0; j < 32; j++) s += ev[j];
        g_esum[blockIdx.x] = s;
    }
}

// ------------------------------ fact1 reduce + fact2 + hidden layer --------
__global__ void kf2fin(const int* __restrict__ med, const float* __restrict__ w1,
                       const float* __restrict__ b1) {
    __shared__ float h[768];
    __shared__ float gsum_s;
    __shared__ int codes_s[63 * 16];
    __shared__ unsigned msk[63];
    int t = threadIdx.x;                            // 1 x 512
    for (int i = t; i < 63 * 16; i += 512) codes_s[i] = med[i];
    if (t < 256) {
        float a = 0.f;
        for (int b = 0; b < 125; b++) a += g_f1p[b][t];
        h[256 + t] = a;
        h[t] = g_query[t];
    }
    if (t == 511) {
        float s = 0.f;
        for (int b = 0; b < 125; b++) s += g_esum[b];
        gsum_s = s;
    }
    __syncthreads();
    if (t < 63) {
        unsigned m = 0;
        for (int k = 0; k < 16; k++) {
            int c = codes_s[t * 16 + k];
            bool dup = false;
            for (int j = 0; j < k; j++) dup |= (codes_s[t * 16 + j] == c);
            if (!dup) m |= (1u << k);
        }
        msk[t] = m;
    }
    __syncthreads();
    if (t < 256) {
        h[256 + t] *= (1.f / gsum_s);               // normalize fact1
        float acc = 0.f;
        for (int i = 0; i < 63; i++) {
            float wv = g_vw[i];
            unsigned m = msk[i];
            #pragma unroll 4
            for (int k = 0; k < 16; k++)
                if ((m >> k) & 1u)
                    acc += wv * g_dm[(size_t)codes_s[i * 16 + k] * 256 + t];
        }
        h[512 + t] = acc;                           // fact2
    }
    __syncthreads();
    float acc = b1[t];
    #pragma unroll 8
    for (int j = 0; j < 768; j++) acc += h[j] * w1[j * 512 + t];
    g_hid[t] = fmaxf(acc, 0.f);
}

// ------------------------------ output layer + sigmoid ---------------------
__global__ void kout(const float* __restrict__ w2, const float* __restrict__ b2,
                     float* __restrict__ out) {
    __shared__ float hid[512];
    int t = threadIdx.x;                            // 32 x 128
    for (int i = t; i < 512; i += 128) hid[i] = g_hid[i];
    __syncthreads();
    int c = blockIdx.x * 128 + t;
    if (c < 4000) {
        float acc = b2[c];
        #pragma unroll 8
        for (int o = 0; o < 512; o++) acc += hid[o] * w2[(size_t)o * 4000 + c];
        out[c] = acc;
        g_sp[c] = 1.f / (1.f + expf(-acc));
    }
}

// ------------------------------ batch_neg quadratic form -------------------
__global__ void kneg(const float* __restrict__ raw) {
    __shared__ __align__(16) float sp_s[4000];
    __shared__ float wred[8];
    int t = threadIdx.x;                            // 500 x 256
    for (int i = t; i < 4000; i += 256) sp_s[i] = g_sp[i];
    __syncthreads();
    int lane = t & 31, w = t >> 5;
    int r = blockIdx.x * 8 + w;
    const float4* rp = (const float4*)(raw + (size_t)r * 4000);
    const float4* sp4 = (const float4*)sp_s;
    float a = 0.f;
    for (int j4 = lane; j4 < 1000; j4 += 32) {
        float4 v = rp[j4];
        float4 s = sp4[j4];
        a += v.x * s.x + v.y * s.y + v.z * s.z + v.w * s.w;
    }
    a = warp_sum(a);
    if (lane == 0) wred[w] = a * sp_s[r];
    __syncthreads();
    if (t == 0) {
        float s = 0.f;
        #pragma unroll
        for (int i = 0; i < 8; i++) s += wred[i];
        g_negp[blockIdx.x] = s;
    }
}

__global__ void kneg2(float* __restrict__ out, int out_size) {
    float s = 0.f;
    for (int b = 0; b < 500; b++) s += g_negp[b];
    if (out_size > 4000) out[4000] = 0.0005f * s;
}

// ---------------------------------------------------------------------------
extern "C" void kernel_launch(void* const* d_in, const int* in_sizes, int n_in,
                              void* d_out, int out_size) {
    const int*   proc    = (const int*)d_in[0];
    const int*   med     = (const int*)d_in[1];
    const float* emb     = (const float*)d_in[2];
    const float* conv_w  = (const float*)d_in[3];
    const float* conv_b  = (const float*)d_in[4];
    const float* wq      = (const float*)d_in[5];
    const float* wk      = (const float*)d_in[6];
    const float* wv      = (const float*)d_in[7];
    const float* wr      = (const float*)d_in[8];
    const float* alpha   = (const float*)d_in[9];
    const float* beta    = (const float*)d_in[10];
    const float* ehr_adj = (const float*)d_in[11];
    const float* ddi_adj = (const float*)d_in[12];
    const float* ddi_raw = (const float*)d_in[13];
    const float* ehr_w1  = (const float*)d_in[14];
    const float* ehr_b1  = (const float*)d_in[15];
    const float* ehr_w2  = (const float*)d_in[16];
    const float* ehr_b2  = (const float*)d_in[17];
    const float* ddi_w1  = (const float*)d_in[18];
    const float* ddi_b1  = (const float*)d_in[19];
    const float* ddi_w2  = (const float*)d_in[20];
    const float* ddi_b2  = (const float*)d_in[21];
    const float* inter   = (const float*)d_in[22];
    const float* out_w1  = (const float*)d_in[23];
    const float* out_b1  = (const float*)d_in[24];
    const float* out_w2  = (const float*)d_in[25];
    const float* out_b2  = (const float*)d_in[26];
    float* out = (float*)d_out;

    kfa<<<64, 128>>>(proc, emb, conv_w, conv_b);
    kfb<<<192, 256>>>(wq, wk, wv);
    kfc<<<1, 256>>>(alpha, beta);
    kfd<<<64, 256>>>(wr);
    kfe<<<1, 256>>>();
    kgcn1<<<8000, 256>>>(ehr_adj, ddi_adj, ehr_w1, ehr_b1, ehr_w2,
                         ddi_w1, ddi_b1, ddi_w2);
    kgcn2<<<4000, 256>>>(ehr_b2, ddi_b2, inter);
    kf1a<<<500, 256>>>();
    kf1b<<<125, 256>>>();
    kf2fin<<<1, 512>>>(med, out_w1, out_b1);
    kout<<<32, 128>>>(out_w2, out_b2, out);
    kneg<<<500, 256>>>(ddi_raw);
    kneg2<<<1, 1>>>(out, out_size);
}

// round 5
// speedup vs baseline: 1.2577x; 1.2577x over previous
#include <cuda_runtime.h>

// ---------------------------------------------------------------------------
// FastRx_wo_Diag: full model in fp32. Round 3: split h@w2 into a register-tiled
// GEMM (kills 2GB of L2 w2 re-reads), grid-merge independent kernels, fuse kfe
// into kfd, fuse fact1 two-pass softmax with block-local max + rescale.
// ---------------------------------------------------------------------------

#define RCAP 128
#define NV   64
#define VMED 4000

// ------------------------------ scratch ------------------------------------
__device__ float g_x[NV * 128];
__device__ float g_q[NV * 256];
__device__ float g_k[NV * 256];
__device__ float g_v[NV * 256];
__device__ float g_gk[256];
__device__ float g_query[256];
__device__ float g_vs[64];                 // visit scores (63 used)

__device__ float g_ellval[2][VMED * RCAP];
__device__ int   g_ellcol[2][VMED * RCAP];
__device__ int   g_elln[2][VMED];
__device__ float g_h[2][VMED * 256];       // relu(A@w1+b1)
__device__ float g_t[2][VMED * 256];       // h @ w2
__device__ float g_dm[VMED * 256];

__device__ float g_f1p[125][256];
__device__ float g_esum[125];
__device__ float g_m[125];
__device__ float g_hid[512];
__device__ float g_sp[VMED];
__device__ float g_negp[500];

// ------------------------------ helpers ------------------------------------
__device__ __forceinline__ float warp_sum(float v) {
    #pragma unroll
    for (int o = 16; o; o >>= 1) v += __shfl_xor_sync(0xffffffffu, v, o);
    return v;
}
__device__ __forceinline__ float warp_max(float v) {
    #pragma unroll
    for (int o = 16; o; o >>= 1) v = fmaxf(v, __shfl_xor_sync(0xffffffffu, v, o));
    return v;
}

// ============================================================================
// L1: adjacency scan -> ELL + h = relu(A@w1+b1)   [blocks 0..7999]
//     + kfa embedding-mean + conv                 [blocks 8000..8063]
// ============================================================================
__global__ void __launch_bounds__(256) k1_scan_front(
    const float* __restrict__ ehr_adj, const float* __restrict__ ddi_adj,
    const float* __restrict__ ehr_w1, const float* __restrict__ ehr_b1,
    const float* __restrict__ ddi_w1, const float* __restrict__ ddi_b1,
    const int* __restrict__ pc, const float* __restrict__ emb,
    const float* __restrict__ cw, const float* __restrict__ cb) {

    __shared__ float val_s[RCAP];
    __shared__ int   col_s[RCAP];
    __shared__ int   woff[8];
    __shared__ int   nnz_s;
    __shared__ float4 part[256];
    __shared__ float xm[130];
    __shared__ int   cs[32];

    int bid = blockIdx.x;
    int t = threadIdx.x, lane = t & 31, w = t >> 5;

    if (bid >= 2 * VMED) {                 // ---- kfa branch ----
        int v = bid - 2 * VMED;
        if (t < 32) cs[t] = pc[v * 32 + t];
        __syncthreads();
        if (t < 128) {
            float a = 0.f;
            #pragma unroll 4
            for (int k = 0; k < 32; k++) a += emb[cs[k] * 128 + t];
            xm[t + 1] = a * (1.f / 32.f);
            if (t == 0) { xm[0] = 0.f; xm[129] = 0.f; }
        }
        __syncthreads();
        if (t < 128) {
            float w0 = cw[0], w1 = cw[1], w2 = cw[2], b = cb[0];
            g_x[v * 128 + t] = fmaxf(w0 * xm[t] + w1 * xm[t + 1] + w2 * xm[t + 2] + b, 0.f);
        }
        return;
    }

    int mat = (bid >= VMED) ? 1 : 0;
    int r = bid - mat * VMED;
    const float* adj = mat ? ddi_adj : ehr_adj;
    const float* w1  = mat ? ddi_w1  : ehr_w1;
    const float* b1  = mat ? ddi_b1  : ehr_b1;

    // --- scan 16 floats per thread (threads 0..249 cover 4000) ---
    float arr[16];
    int cnt = 0;
    const float4* rowp = (const float4*)(adj + (size_t)r * 4000);
    if (t < 250) {
        #pragma unroll
        for (int j = 0; j < 4; j++) {
            float4 q = rowp[t * 4 + j];
            arr[j * 4 + 0] = q.x; arr[j * 4 + 1] = q.y;
            arr[j * 4 + 2] = q.z; arr[j * 4 + 3] = q.w;
        }
        #pragma unroll
        for (int j = 0; j < 16; j++) cnt += (arr[j] != 0.f);
    } else {
        #pragma unroll
        for (int j = 0; j < 16; j++) arr[j] = 0.f;
    }
    int incl = cnt;
    #pragma unroll
    for (int o = 1; o < 32; o <<= 1) {
        int x = __shfl_up_sync(0xffffffffu, incl, o);
        if (lane >= o) incl += x;
    }
    if (lane == 31) woff[w] = incl;
    __syncthreads();
    if (t == 0) {
        int s = 0;
        #pragma unroll
        for (int i = 0; i < 8; i++) { int c = woff[i]; woff[i] = s; s += c; }
        nnz_s = (s < RCAP) ? s : RCAP;
    }
    __syncthreads();
    int pos = woff[w] + incl - cnt;
    if (t < 250) {
        #pragma unroll
        for (int j = 0; j < 16; j++) {
            float vv = arr[j];
            if (vv != 0.f) {
                if (pos < RCAP) { val_s[pos] = vv; col_s[pos] = t * 16 + j; }
                pos++;
            }
        }
    }
    __syncthreads();
    int n = nnz_s;
    for (int i = t; i < n; i += 256) {
        g_ellval[mat][r * RCAP + i] = val_s[i];
        g_ellcol[mat][r * RCAP + i] = col_s[i];
    }
    if (t == 0) g_elln[mat][r] = n;

    // --- h = relu(spmm + b1): 4 nnz segments x 64 col-quads -----------------
    int eg = (t & 63) << 2;
    int seg = t >> 6;
    float4 acc = {0.f, 0.f, 0.f, 0.f};
    int i0 = (n * seg) >> 2, i1 = (n * (seg + 1)) >> 2;
    for (int i = i0; i < i1; i++) {
        float vv = val_s[i];
        const float4 wv = *(const float4*)(w1 + (size_t)col_s[i] * 256 + eg);
        acc.x += vv * wv.x; acc.y += vv * wv.y; acc.z += vv * wv.z; acc.w += vv * wv.w;
    }
    part[t] = acc;
    __syncthreads();
    if (seg == 0) {
        float4 p0 = part[t], p1 = part[t + 64], p2 = part[t + 128], p3 = part[t + 192];
        float4 bb = *(const float4*)(b1 + eg);
        float4 hh;
        hh.x = fmaxf(p0.x + p1.x + p2.x + p3.x + bb.x, 0.f);
        hh.y = fmaxf(p0.y + p1.y + p2.y + p3.y + bb.y, 0.f);
        hh.z = fmaxf(p0.z + p1.z + p2.z + p3.z + bb.z, 0.f);
        hh.w = fmaxf(p0.w + p1.w + p2.w + p3.w + bb.w, 0.f);
        *(float4*)(g_h[mat] + (size_t)r * 256 + eg) = hh;
    }
}

// ============================================================================
// L2: t = h @ w2 register-tiled GEMM (M=16/block)  [blocks 0..499]
//     + kfb q,k,v = x @ W                          [blocks 500..691]
// ============================================================================
__global__ void __launch_bounds__(256) k2_gemm_qkv(
    const float* __restrict__ ehr_w2, const float* __restrict__ ddi_w2,
    const float* __restrict__ wq, const float* __restrict__ wk,
    const float* __restrict__ wv) {
    __shared__ float h_s[16 * 256];
    __shared__ float xr[128];
    int t = threadIdx.x, bid = blockIdx.x;

    if (bid < 500) {                        // ---- GEMM tile ----
        int mat = bid / 250, r0 = (bid % 250) * 16;
        const float* w2 = mat ? ddi_w2 : ehr_w2;
        const float* hsrc = g_h[mat];
        int row = t >> 4;
        const float4* src = (const float4*)(hsrc + (size_t)(r0 + row) * 256);
        float4* dstS = (float4*)(h_s + row * 256);
        #pragma unroll
        for (int j = 0; j < 4; j++) {
            int qi = (t & 15) + j * 16;
            dstS[qi] = src[qi];
        }
        __syncthreads();
        int cg = t & 63, rg4 = (t >> 6) * 4;
        const float4* w2v = (const float4*)w2 + cg;
        const float* hr = h_s + rg4 * 256;
        float4 a0 = {0,0,0,0}, a1 = a0, a2 = a0, a3 = a0;
        #pragma unroll 4
        for (int k = 0; k < 256; k++) {
            float4 wv4 = w2v[(size_t)k * 64];
            float h0 = hr[k], h1 = hr[256 + k], h2 = hr[512 + k], h3 = hr[768 + k];
            a0.x += h0 * wv4.x; a0.y += h0 * wv4.y; a0.z += h0 * wv4.z; a0.w += h0 * wv4.w;
            a1.x += h1 * wv4.x; a1.y += h1 * wv4.y; a1.z += h1 * wv4.z; a1.w += h1 * wv4.w;
            a2.x += h2 * wv4.x; a2.y += h2 * wv4.y; a2.z += h2 * wv4.z; a2.w += h2 * wv4.w;
            a3.x += h3 * wv4.x; a3.y += h3 * wv4.y; a3.z += h3 * wv4.z; a3.w += h3 * wv4.w;
        }
        float4* dst = (float4*)g_t[mat];
        dst[(size_t)(r0 + rg4 + 0) * 64 + cg] = a0;
        dst[(size_t)(r0 + rg4 + 1) * 64 + cg] = a1;
        dst[(size_t)(r0 + rg4 + 2) * 64 + cg] = a2;
        dst[(size_t)(r0 + rg4 + 3) * 64 + cg] = a3;
    } else {                                // ---- kfb branch ----
        int b2 = bid - 500, v = b2 & 63, m = b2 >> 6;
        const float* W = (m == 0) ? wq : (m == 1) ? wk : wv;
        float* D = (m == 0) ? g_q : (m == 1) ? g_k : g_v;
        if (t < 128) xr[t] = g_x[v * 128 + t];
        __syncthreads();
        float a0 = 0.f, a1 = 0.f, a2 = 0.f, a3 = 0.f;
        #pragma unroll 8
        for (int f = 0; f < 128; f += 4) {
            a0 += xr[f]     * W[(f)     * 256 + t];
            a1 += xr[f + 1] * W[(f + 1) * 256 + t];
            a2 += xr[f + 2] * W[(f + 2) * 256 + t];
            a3 += xr[f + 3] * W[(f + 3) * 256 + t];
        }
        D[v * 256 + t] = (a0 + a1) + (a2 + a3);
    }
}

// ============================================================================
// L3: dm = spmm(A_e, t_e)+b2e - inter*(spmm(A_d, t_d)+b2d)   [blocks 0..3999]
//     + kfc fastformer global vectors                         [block 4000]
// ============================================================================
__global__ void __launch_bounds__(256) k3_gcn2_ff(
    const float* __restrict__ b2e, const float* __restrict__ b2d,
    const float* __restrict__ inter,
    const float* __restrict__ alpha, const float* __restrict__ beta) {
    __shared__ float ve[RCAP]; __shared__ int ce[RCAP];
    __shared__ float vd[RCAP]; __shared__ int cd[RCAP];
    __shared__ float4 part[256];
    __shared__ float m1[64], rd1[64], gqs[256], m2[64], rd2[64];

    int bid = blockIdx.x;
    int t = threadIdx.x, lane = t & 31, w = t >> 5;

    if (bid == VMED) {                      // ---- kfc branch ----
        const float scale = 0.0625f;
        for (int rr = 0; rr < 8; rr++) {
            int r = w * 8 + rr;
            float z[8], mx = -1e30f;
            #pragma unroll
            for (int j = 0; j < 8; j++) {
                int e = lane + j * 32;
                z[j] = g_q[r * 256 + e] * alpha[e] * scale;
                mx = fmaxf(mx, z[j]);
            }
            mx = warp_max(mx);
            float s = 0.f;
            #pragma unroll
            for (int j = 0; j < 8; j++) s += expf(z[j] - mx);
            s = warp_sum(s);
            if (lane == 0) { m1[r] = mx; rd1[r] = 1.f / s; }
        }
        __syncthreads();
        {
            float a = alpha[t] * scale, acc = 0.f;
            for (int v = 0; v < 64; v++) {
                float q = g_q[v * 256 + t];
                acc += q * expf(q * a - m1[v]) * rd1[v];
            }
            gqs[t] = acc;
        }
        __syncthreads();
        for (int rr = 0; rr < 8; rr++) {
            int r = w * 8 + rr;
            float z[8], mx = -1e30f;
            #pragma unroll
            for (int j = 0; j < 8; j++) {
                int e = lane + j * 32;
                z[j] = gqs[e] * g_k[r * 256 + e] * beta[e] * scale;
                mx = fmaxf(mx, z[j]);
            }
            mx = warp_max(mx);
            float s = 0.f;
            #pragma unroll
            for (int j = 0; j < 8; j++) s += expf(z[j] - mx);
            s = warp_sum(s);
            if (lane == 0) { m2[r] = mx; rd2[r] = 1.f / s; }
        }
        __syncthreads();
        {
            float bsc = beta[t] * scale, gq_e = gqs[t], acc = 0.f;
            for (int v = 0; v < 64; v++) {
                float p = gq_e * g_k[v * 256 + t];
                acc += p * expf(p * bsc - m2[v]) * rd2[v];
            }
            g_gk[t] = acc;
        }
        return;
    }

    int r = bid;
    int ne = g_elln[0][r], nd = g_elln[1][r];
    for (int i = t; i < ne; i += 256) { ve[i] = g_ellval[0][r * RCAP + i]; ce[i] = g_ellcol[0][r * RCAP + i]; }
    for (int i = t; i < nd; i += 256) { vd[i] = g_ellval[1][r * RCAP + i]; cd[i] = g_ellcol[1][r * RCAP + i]; }
    __syncthreads();
    int eg = (t & 63) << 2, seg = t >> 6;

    float4 acc = {0.f, 0.f, 0.f, 0.f};
    for (int i = (ne * seg) >> 2; i < (ne * (seg + 1)) >> 2; i++) {
        float vv = ve[i];
        const float4 tv = *(const float4*)(&g_t[0][(size_t)ce[i] * 256 + eg]);
        acc.x += vv * tv.x; acc.y += vv * tv.y; acc.z += vv * tv.z; acc.w += vv * tv.w;
    }
    part[t] = acc;
    __syncthreads();
    float4 acce = {0.f, 0.f, 0.f, 0.f};
    if (seg == 0) {
        float4 p0 = part[t], p1 = part[t + 64], p2 = part[t + 128], p3 = part[t + 192];
        acce.x = p0.x + p1.x + p2.x + p3.x; acce.y = p0.y + p1.y + p2.y + p3.y;
        acce.z = p0.z + p1.z + p2.z + p3.z; acce.w = p0.w + p1.w + p2.w + p3.w;
    }
    __syncthreads();
    float4 a2 = {0.f, 0.f, 0.f, 0.f};
    for (int i = (nd * seg) >> 2; i < (nd * (seg + 1)) >> 2; i++) {
        float vv = vd[i];
        const float4 tv = *(const float4*)(&g_t[1][(size_t)cd[i] * 256 + eg]);
        a2.x += vv * tv.x; a2.y += vv * tv.y; a2.z += vv * tv.z; a2.w += vv * tv.w;
    }
    part[t] = a2;
    __syncthreads();
    if (seg == 0) {
        float4 p0 = part[t], p1 = part[t + 64], p2 = part[t + 128], p3 = part[t + 192];
        float4 accd;
        accd.x = p0.x + p1.x + p2.x + p3.x; accd.y = p0.y + p1.y + p2.y + p3.y;
        accd.z = p0.z + p1.z + p2.z + p3.z; accd.w = p0.w + p1.w + p2.w + p3.w;
        float iv = inter[0];
        float4 be = *(const float4*)(b2e + eg);
        float4 bd = *(const float4*)(b2d + eg);
        float4 o;
        o.x = (acce.x + be.x) - iv * (accd.x + bd.x);
        o.y = (acce.y + be.y) - iv * (accd.y + bd.y);
        o.z = (acce.z + be.z) - iv * (accd.z + bd.z);
        o.w = (acce.w + be.w) - iv * (accd.w + bd.w);
        *(float4*)(&g_dm[(size_t)r * 256 + eg]) = o;
    }
}

// ============================================================================
// L4: feat row v + feat row 63 (shared wr loads), visit score, query  (64 blk)
// ============================================================================
__global__ void __launch_bounds__(256) k4_feat(const float* __restrict__ wr) {
    __shared__ float gvr[256], gv63[256], red[8];
    int v = blockIdx.x, t = threadIdx.x, lane = t & 31, w = t >> 5;
    float gk = g_gk[t];
    gvr[t]  = gk * g_v[v * 256 + t];
    gv63[t] = gk * g_v[63 * 256 + t];
    __syncthreads();
    float ar0 = 0.f, ar1 = 0.f, b0 = 0.f, b1 = 0.f;
    #pragma unroll 4
    for (int e = 0; e < 256; e += 2) {
        float w0 = wr[(e)     * 256 + t];
        float w1 = wr[(e + 1) * 256 + t];
        ar0 += gvr[e]     * w0;  b0 += gv63[e]     * w0;
        ar1 += gvr[e + 1] * w1;  b1 += gv63[e + 1] * w1;
    }
    float fr  = g_q[v * 256 + t]  + (ar0 + ar1);
    float f63 = g_q[63 * 256 + t] + (b0 + b1);
    if (v == 63) g_query[t] = fr;
    float p = warp_sum(fr * f63);
    if (lane == 0) red[w] = p;
    __syncthreads();
    if (t == 0 && v < 63) {
        float s = 0.f;
        #pragma unroll
        for (int i = 0; i < 8; i++) s += red[i];
        g_vs[v] = s;
    }
}

// ============================================================================
// L5: fact1 fused: scores + block-local softmax partials   (125 blocks x 32 rows)
// ============================================================================
__global__ void __launch_bounds__(256) k5_fact1() {
    __shared__ float qys[256], sc[32], evs[32];
    int t = threadIdx.x, lane = t & 31, w = t >> 5, r0 = blockIdx.x * 32;
    qys[t] = g_query[t];
    __syncthreads();
    const float4* qp = (const float4*)qys;
    #pragma unroll
    for (int jr = 0; jr < 4; jr++) {
        int j = w * 4 + jr;
        const float4* dp = (const float4*)(g_dm + (size_t)(r0 + j) * 256);
        float4 d0 = dp[lane], q0 = qp[lane];
        float4 d1 = dp[lane + 32], q1 = qp[lane + 32];
        float a = d0.x * q0.x + d0.y * q0.y + d0.z * q0.z + d0.w * q0.w
                + d1.x * q1.x + d1.y * q1.y + d1.z * q1.z + d1.w * q1.w;
        a = warp_sum(a);
        if (lane == 0) sc[j] = a;
    }
    __syncthreads();
    if (t < 32) {
        float s0 = sc[t];
        float m = warp_max(s0);
        float e = expf(s0 - m);
        evs[t] = e;
        float s = warp_sum(e);
        if (t == 0) { g_m[blockIdx.x] = m; g_esum[blockIdx.x] = s; }
    }
    __syncthreads();
    float acc = 0.f;
    #pragma unroll 4
    for (int j = 0; j < 32; j++) acc += evs[j] * g_dm[(size_t)(r0 + j) * 256 + t];
    g_f1p[blockIdx.x][t] = acc;
}

// ============================================================================
// L6: final reductions + fact2 + hidden layer   (1 block x 512)
// ============================================================================
__global__ void __launch_bounds__(512) k6_final(
    const int* __restrict__ med, const float* __restrict__ w1,
    const float* __restrict__ b1) {
    __shared__ float h[768];
    __shared__ int codes[63 * 16];
    __shared__ unsigned msk[63];
    __shared__ float mb[125], scb[125], esb[125], vsv[63], vwe[63];
    __shared__ float gM, gden, vmax, vsum;
    int t = threadIdx.x;

    for (int i = t; i < 63 * 16; i += 512) codes[i] = med[i];
    if (t < 125) { mb[t] = g_m[t]; esb[t] = g_esum[t]; }
    if (t >= 128 && t < 191) vsv[t - 128] = g_vs[t - 128];
    __syncthreads();
    if (t == 0) { float M = -1e30f; for (int b = 0; b < 125; b++) M = fmaxf(M, mb[b]); gM = M; }
    if (t == 1) { float m = -1e30f; for (int i = 0; i < 63; i++) m = fmaxf(m, vsv[i]); vmax = m; }
    __syncthreads();
    if (t < 125) scb[t] = expf(mb[t] - gM);
    if (t >= 128 && t < 191) vwe[t - 128] = expf(vsv[t - 128] - vmax);
    if (t >= 192 && t < 255) {   // dup mask
        int i = t - 192;
        unsigned m = 0;
        for (int k = 0; k < 16; k++) {
            int c = codes[i * 16 + k];
            bool dup = false;
            for (int j = 0; j < k; j++) dup |= (codes[i * 16 + j] == c);
            if (!dup) m |= (1u << k);
        }
        msk[i] = m;
    }
    __syncthreads();
    if (t == 0) { float s = 0.f; for (int b = 0; b < 125; b++) s += scb[b] * esb[b]; gden = 1.f / s; }
    if (t == 1) { float s = 0.f; for (int i = 0; i < 63; i++) s += vwe[i]; vsum = 1.f / s; }
    __syncthreads();
    if (t < 256) {
        float a = 0.f;
        for (int b = 0; b < 125; b++) a += scb[b] * g_f1p[b][t];
        h[256 + t] = a * gden;
        h[t] = g_query[t];
        // fact2 (scaled by vsum at the end; softmax weights linear)
        float acc = 0.f;
        for (int i = 0; i < 63; i++) {
            float wv = vwe[i];
            unsigned m = msk[i];
            #pragma unroll 4
            for (int k = 0; k < 16; k++)
                if ((m >> k) & 1u)
                    acc += wv * g_dm[(size_t)codes[i * 16 + k] * 256 + t];
        }
        h[512 + t] = acc * vsum;
    }
    __syncthreads();
    float a0 = 0.f, a1 = 0.f, a2 = 0.f, a3 = 0.f;
    #pragma unroll 4
    for (int j = 0; j < 768; j += 4) {
        a0 += h[j]     * w1[(j)     * 512 + t];
        a1 += h[j + 1] * w1[(j + 1) * 512 + t];
        a2 += h[j + 2] * w1[(j + 2) * 512 + t];
        a3 += h[j + 3] * w1[(j + 3) * 512 + t];
    }
    g_hid[t] = fmaxf((a0 + a1) + (a2 + a3) + b1[t], 0.f);
}

// ============================================================================
// L7: output layer + sigmoid   (32 blocks x 512, K split over 4 warpsets)
// ============================================================================
__global__ void __launch_bounds__(512) k7_out(
    const float* __restrict__ w2, const float* __restrict__ b2,
    float* __restrict__ out) {
    __shared__ float hid[512];
    __shared__ float part[512];
    int t = threadIdx.x;
    hid[t] = g_hid[t];
    __syncthreads();
    int c = blockIdx.x * 128 + (t & 127);
    int os = t >> 7;
    float a0 = 0.f, a1 = 0.f;
    if (c < 4000) {
        #pragma unroll 4
        for (int o = os * 128; o < os * 128 + 128; o += 2) {
            a0 += hid[o]     * w2[(size_t)(o)     * 4000 + c];
            a1 += hid[o + 1] * w2[(size_t)(o + 1) * 4000 + c];
        }
    }
    part[t] = a0 + a1;
    __syncthreads();
    if (os == 0 && c < 4000) {
        float r = part[t] + part[t + 128] + part[t + 256] + part[t + 384] + b2[c];
        out[c] = r;
        g_sp[c] = 1.f / (1.f + expf(-r));
    }
}

// ============================================================================
// L8: batch_neg partials   (500 blocks x 256)
// ============================================================================
__global__ void __launch_bounds__(256) k8_neg(const float* __restrict__ raw) {
    __shared__ __align__(16) float sp_s[4000];
    __shared__ float wred[8];
    int t = threadIdx.x;
    for (int i = t; i < 4000; i += 256) sp_s[i] = g_sp[i];
    __syncthreads();
    int lane = t & 31, w = t >> 5;
    int r = blockIdx.x * 8 + w;
    const float4* rp = (const float4*)(raw + (size_t)r * 4000);
    const float4* sp4 = (const float4*)sp_s;
    float a = 0.f;
    for (int j4 = lane; j4 < 1000; j4 += 32) {
        float4 v = rp[j4];
        float4 s = sp4[j4];
        a += v.x * s.x + v.y * s.y + v.z * s.z + v.w * s.w;
    }
    a = warp_sum(a);
    if (lane == 0) wred[w] = a * sp_s[r];
    __syncthreads();
    if (t == 0) {
        float s = 0.f;
        #pragma unroll
        for (int i = 0; i < 8; i++) s += wred[i];
        g_negp[blockIdx.x] = s;
    }
}

// L9: final scalar
__global__ void __launch_bounds__(512) k9_neg2(float* __restrict__ out, int out_size) {
    __shared__ float p[512];
    int t = threadIdx.x;
    p[t] = (t < 500) ? g_negp[t] : 0.f;
    __syncthreads();
    if (t == 0) {
        float s = 0.f;
        for (int i = 0; i < 500; i++) s += p[i];
        if (out_size > 4000) out[4000] = 0.0005f * s;
    }
}

// ---------------------------------------------------------------------------
extern "C" void kernel_launch(void* const* d_in, const int* in_sizes, int n_in,
                              void* d_out, int out_size) {
    const int*   proc    = (const int*)d_in[0];
    const int*   med     = (const int*)d_in[1];
    const float* emb     = (const float*)d_in[2];
    const float* conv_w  = (const float*)d_in[3];
    const float* conv_b  = (const float*)d_in[4];
    const float* wq      = (const float*)d_in[5];
    const float* wk      = (const float*)d_in[6];
    const float* wv      = (const float*)d_in[7];
    const float* wr      = (const float*)d_in[8];
    const float* alpha   = (const float*)d_in[9];
    const float* beta    = (const float*)d_in[10];
    const float* ehr_adj = (const float*)d_in[11];
    const float* ddi_adj = (const float*)d_in[12];
    const float* ddi_raw = (const float*)d_in[13];
    const float* ehr_w1  = (const float*)d_in[14];
    const float* ehr_b1  = (const float*)d_in[15];
    const float* ehr_w2  = (const float*)d_in[16];
    const float* ehr_b2  = (const float*)d_in[17];
    const float* ddi_w1  = (const float*)d_in[18];
    const float* ddi_b1  = (const float*)d_in[19];
    const float* ddi_w2  = (const float*)d_in[20];
    const float* ddi_b2  = (const float*)d_in[21];
    const float* inter   = (const float*)d_in[22];
    const float* out_w1  = (const float*)d_in[23];
    const float* out_b1  = (const float*)d_in[24];
    const float* out_w2  = (const float*)d_in[25];
    const float* out_b2  = (const float*)d_in[26];
    float* out = (float*)d_out;

    k1_scan_front<<<2 * VMED + 64, 256>>>(ehr_adj, ddi_adj, ehr_w1, ehr_b1,
                                          ddi_w1, ddi_b1, proc, emb, conv_w, conv_b);
    k2_gemm_qkv<<<692, 256>>>(ehr_w2, ddi_w2, wq, wk, wv);
    k3_gcn2_ff<<<VMED + 1, 256>>>(ehr_b2, ddi_b2, inter, alpha, beta);
    k4_feat<<<64, 256>>>(wr);
    k5_fact1<<<125, 256>>>();
    k6_final<<<1, 512>>>(med, out_w1, out_b1);
    k7_out<<<32, 512>>>(out_w2, out_b2, out);
    k8_neg<<<500, 256>>>(ddi_raw);
    k9_neg2<<<1, 512>>>(out, out_size);
}

// round 6
// speedup vs baseline: 1.7707x; 1.4079x over previous
#include <cuda_runtime.h>

// ---------------------------------------------------------------------------
// FastRx_wo_Diag fp32. Round 5: kill latency-bound tails (k4/k6/k7), f32x2
// packed-FMA GEMM for h@w2, ELL-derived batch_neg (no 64MB ddi_raw pass),
// fact2 parallelized into k5, fused final reduction.
// ---------------------------------------------------------------------------

#define RCAP 128
#define NV   64
#define VMED 4000

// ------------------------------ scratch ------------------------------------
__device__ float g_x[NV * 128];
__device__ float g_q[NV * 256];
__device__ float g_k[NV * 256];
__device__ float g_v[NV * 256];
__device__ float g_gk[256];
__device__ float g_query[256];
__device__ float g_vs[64];

__device__ float g_ellval[2][VMED * RCAP];
__device__ int   g_ellcol[2][VMED * RCAP];
__device__ int   g_elln[2][VMED];
__device__ float g_h[2][VMED * 256];
__device__ float g_t[2][VMED * 256];
__device__ float g_dm[VMED * 256];

__device__ float g_f1p[125][256];
__device__ float g_esum[125];
__device__ float g_m[125];
__device__ float g_f2p[63][256];
__device__ float g_hid[512];
__device__ float g_sp[VMED];
__device__ float g_negp[32];
__device__ int   g_ctr;

// ------------------------------ helpers ------------------------------------
__device__ __forceinline__ float warp_sum(float v) {
    #pragma unroll
    for (int o = 16; o; o >>= 1) v += __shfl_xor_sync(0xffffffffu, v, o);
    return v;
}
__device__ __forceinline__ float warp_max(float v) {
    #pragma unroll
    for (int o = 16; o; o >>= 1) v = fmaxf(v, __shfl_xor_sync(0xffffffffu, v, o));
    return v;
}
__device__ __forceinline__ unsigned long long dup2(float x) {
    unsigned long long r;
    asm("mov.b64 %0, {%1, %1};" : "=l"(r) : "f"(x));
    return r;
}
__device__ __forceinline__ float2 unp2(unsigned long long v) {
    float2 f;
    asm("mov.b64 {%0, %1}, %2;" : "=f"(f.x), "=f"(f.y) : "l"(v));
    return f;
}
#define FMA2(acc, a, b) asm("fma.rn.f32x2 %0, %1, %2, %0;" : "+l"(acc) : "l"(a), "l"(b))

// ============================================================================
// L1: adjacency scan -> ELL + h = relu(A@w1+b1)   [blocks 0..7999]
//     + kfa embedding-mean + conv                 [blocks 8000..8063]
// ============================================================================
__global__ void __launch_bounds__(256) k1_scan_front(
    const float* __restrict__ ehr_adj, const float* __restrict__ ddi_adj,
    const float* __restrict__ ehr_w1, const float* __restrict__ ehr_b1,
    const float* __restrict__ ddi_w1, const float* __restrict__ ddi_b1,
    const int* __restrict__ pc, const float* __restrict__ emb,
    const float* __restrict__ cw, const float* __restrict__ cb) {

    __shared__ float val_s[RCAP];
    __shared__ int   col_s[RCAP];
    __shared__ int   woff[8];
    __shared__ int   nnz_s;
    __shared__ float4 part[256];
    __shared__ float xm[130];
    __shared__ int   cs[32];

    int bid = blockIdx.x;
    int t = threadIdx.x, lane = t & 31, w = t >> 5;

    if (bid >= 2 * VMED) {                 // ---- kfa branch ----
        int v = bid - 2 * VMED;
        if (t < 32) cs[t] = pc[v * 32 + t];
        __syncthreads();
        if (t < 128) {
            float a = 0.f;
            #pragma unroll 4
            for (int k = 0; k < 32; k++) a += emb[cs[k] * 128 + t];
            xm[t + 1] = a * (1.f / 32.f);
            if (t == 0) { xm[0] = 0.f; xm[129] = 0.f; }
        }
        __syncthreads();
        if (t < 128) {
            float w0 = cw[0], w1 = cw[1], w2 = cw[2], b = cb[0];
            g_x[v * 128 + t] = fmaxf(w0 * xm[t] + w1 * xm[t + 1] + w2 * xm[t + 2] + b, 0.f);
        }
        return;
    }

    int mat = (bid >= VMED) ? 1 : 0;
    int r = bid - mat * VMED;
    const float* adj = mat ? ddi_adj : ehr_adj;
    const float* w1  = mat ? ddi_w1  : ehr_w1;
    const float* b1  = mat ? ddi_b1  : ehr_b1;

    float arr[16];
    int cnt = 0;
    const float4* rowp = (const float4*)(adj + (size_t)r * 4000);
    if (t < 250) {
        #pragma unroll
        for (int j = 0; j < 4; j++) {
            float4 q = rowp[t * 4 + j];
            arr[j * 4 + 0] = q.x; arr[j * 4 + 1] = q.y;
            arr[j * 4 + 2] = q.z; arr[j * 4 + 3] = q.w;
        }
        #pragma unroll
        for (int j = 0; j < 16; j++) cnt += (arr[j] != 0.f);
    } else {
        #pragma unroll
        for (int j = 0; j < 16; j++) arr[j] = 0.f;
    }
    int incl = cnt;
    #pragma unroll
    for (int o = 1; o < 32; o <<= 1) {
        int x = __shfl_up_sync(0xffffffffu, incl, o);
        if (lane >= o) incl += x;
    }
    if (lane == 31) woff[w] = incl;
    __syncthreads();
    if (t == 0) {
        int s = 0;
        #pragma unroll
        for (int i = 0; i < 8; i++) { int c = woff[i]; woff[i] = s; s += c; }
        nnz_s = (s < RCAP) ? s : RCAP;
    }
    __syncthreads();
    int pos = woff[w] + incl - cnt;
    if (t < 250) {
        #pragma unroll
        for (int j = 0; j < 16; j++) {
            float vv = arr[j];
            if (vv != 0.f) {
                if (pos < RCAP) { val_s[pos] = vv; col_s[pos] = t * 16 + j; }
                pos++;
            }
        }
    }
    __syncthreads();
    int n = nnz_s;
    for (int i = t; i < n; i += 256) {
        g_ellval[mat][r * RCAP + i] = val_s[i];
        g_ellcol[mat][r * RCAP + i] = col_s[i];
    }
    if (t == 0) g_elln[mat][r] = n;

    int eg = (t & 63) << 2;
    int seg = t >> 6;
    float4 acc = {0.f, 0.f, 0.f, 0.f};
    int i0 = (n * seg) >> 2, i1 = (n * (seg + 1)) >> 2;
    for (int i = i0; i < i1; i++) {
        float vv = val_s[i];
        const float4 wv = *(const float4*)(w1 + (size_t)col_s[i] * 256 + eg);
        acc.x += vv * wv.x; acc.y += vv * wv.y; acc.z += vv * wv.z; acc.w += vv * wv.w;
    }
    part[t] = acc;
    __syncthreads();
    if (seg == 0) {
        float4 p0 = part[t], p1 = part[t + 64], p2 = part[t + 128], p3 = part[t + 192];
        float4 bb = *(const float4*)(b1 + eg);
        float4 hh;
        hh.x = fmaxf(p0.x + p1.x + p2.x + p3.x + bb.x, 0.f);
        hh.y = fmaxf(p0.y + p1.y + p2.y + p3.y + bb.y, 0.f);
        hh.z = fmaxf(p0.z + p1.z + p2.z + p3.z + bb.z, 0.f);
        hh.w = fmaxf(p0.w + p1.w + p2.w + p3.w + bb.w, 0.f);
        *(float4*)(g_h[mat] + (size_t)r * 256 + eg) = hh;
    }
}

// ============================================================================
// L2: t = h @ w2 GEMM (M=16/block, fma.f32x2)  [blocks 0..499]
//     + kfb q,k,v = x @ W                      [blocks 500..691]
// ============================================================================
__global__ void __launch_bounds__(256) k2_gemm_qkv(
    const float* __restrict__ ehr_w2, const float* __restrict__ ddi_w2,
    const float* __restrict__ wq, const float* __restrict__ wk,
    const float* __restrict__ wv) {
    __shared__ unsigned long long h2_s[16 * 256];   // h duplicated into both lanes
    __shared__ float xr[128];
    int t = threadIdx.x, bid = blockIdx.x;

    if (bid < 500) {                        // ---- GEMM tile ----
        int mat = bid / 250, r0 = (bid % 250) * 16;
        const float* w2 = mat ? ddi_w2 : ehr_w2;
        const float* hsrc = g_h[mat];
        int row = t >> 4;
        const float4* src = (const float4*)(hsrc + (size_t)(r0 + row) * 256);
        unsigned long long* dstS = h2_s + row * 256;
        #pragma unroll
        for (int j = 0; j < 4; j++) {
            int qi = (t & 15) + j * 16;
            float4 hv = src[qi];
            dstS[qi * 4 + 0] = dup2(hv.x);
            dstS[qi * 4 + 1] = dup2(hv.y);
            dstS[qi * 4 + 2] = dup2(hv.z);
            dstS[qi * 4 + 3] = dup2(hv.w);
        }
        __syncthreads();
        int cg = t & 63, rg4 = (t >> 6) * 4;
        const ulonglong2* w2v = (const ulonglong2*)w2 + cg;
        const unsigned long long* hr = h2_s + rg4 * 256;
        unsigned long long a00 = 0ULL, a01 = 0ULL, a10 = 0ULL, a11 = 0ULL;
        unsigned long long a20 = 0ULL, a21 = 0ULL, a30 = 0ULL, a31 = 0ULL;
        #pragma unroll 4
        for (int k = 0; k < 256; k++) {
            ulonglong2 wv2 = w2v[(size_t)k * 64];
            unsigned long long h0 = hr[k], h1 = hr[256 + k];
            unsigned long long h2 = hr[512 + k], h3 = hr[768 + k];
            FMA2(a00, h0, wv2.x); FMA2(a01, h0, wv2.y);
            FMA2(a10, h1, wv2.x); FMA2(a11, h1, wv2.y);
            FMA2(a20, h2, wv2.x); FMA2(a21, h2, wv2.y);
            FMA2(a30, h3, wv2.x); FMA2(a31, h3, wv2.y);
        }
        float4* dst = (float4*)g_t[mat];
        float2 lo, hi;
        lo = unp2(a00); hi = unp2(a01);
        dst[(size_t)(r0 + rg4 + 0) * 64 + cg] = make_float4(lo.x, lo.y, hi.x, hi.y);
        lo = unp2(a10); hi = unp2(a11);
        dst[(size_t)(r0 + rg4 + 1) * 64 + cg] = make_float4(lo.x, lo.y, hi.x, hi.y);
        lo = unp2(a20); hi = unp2(a21);
        dst[(size_t)(r0 + rg4 + 2) * 64 + cg] = make_float4(lo.x, lo.y, hi.x, hi.y);
        lo = unp2(a30); hi = unp2(a31);
        dst[(size_t)(r0 + rg4 + 3) * 64 + cg] = make_float4(lo.x, lo.y, hi.x, hi.y);
    } else {                                // ---- kfb branch ----
        int b2 = bid - 500, v = b2 & 63, m = b2 >> 6;
        const float* W = (m == 0) ? wq : (m == 1) ? wk : wv;
        float* D = (m == 0) ? g_q : (m == 1) ? g_k : g_v;
        if (t < 128) xr[t] = g_x[v * 128 + t];
        __syncthreads();
        float a0 = 0.f, a1 = 0.f, a2 = 0.f, a3 = 0.f;
        #pragma unroll 8
        for (int f = 0; f < 128; f += 4) {
            a0 += xr[f]     * W[(f)     * 256 + t];
            a1 += xr[f + 1] * W[(f + 1) * 256 + t];
            a2 += xr[f + 2] * W[(f + 2) * 256 + t];
            a3 += xr[f + 3] * W[(f + 3) * 256 + t];
        }
        D[v * 256 + t] = (a0 + a1) + (a2 + a3);
    }
}

// ============================================================================
// L3: dm = spmm(A_e,t_e)+b2e - inter*(spmm(A_d,t_d)+b2d)  [blocks 0..3999, 512t]
//     + kfc fastformer global vectors                      [block 4000]
// ============================================================================
__global__ void __launch_bounds__(512) k3_gcn2_ff(
    const float* __restrict__ b2e, const float* __restrict__ b2d,
    const float* __restrict__ inter,
    const float* __restrict__ alpha, const float* __restrict__ beta) {
    __shared__ float ve[RCAP]; __shared__ int ce[RCAP];
    __shared__ float vd[RCAP]; __shared__ int cd[RCAP];
    __shared__ float4 part[512];
    __shared__ float m1[64], rd1[64], gqs[256], m2[64], rd2[64];

    int bid = blockIdx.x;
    int t = threadIdx.x, lane = t & 31, w = t >> 5;

    if (bid == VMED) {                      // ---- kfc (guarded for 512 thr) ----
        const float scale = 0.0625f;
        if (t < 256) {
            for (int rr = 0; rr < 8; rr++) {
                int r = w * 8 + rr;
                float z[8], mx = -1e30f;
                #pragma unroll
                for (int j = 0; j < 8; j++) {
                    int e = lane + j * 32;
                    z[j] = g_q[r * 256 + e] * alpha[e] * scale;
                    mx = fmaxf(mx, z[j]);
                }
                mx = warp_max(mx);
                float s = 0.f;
                #pragma unroll
                for (int j = 0; j < 8; j++) s += expf(z[j] - mx);
                s = warp_sum(s);
                if (lane == 0) { m1[r] = mx; rd1[r] = 1.f / s; }
            }
        }
        __syncthreads();
        if (t < 256) {
            float a = alpha[t] * scale, acc = 0.f;
            for (int v = 0; v < 64; v++) {
                float q = g_q[v * 256 + t];
                acc += q * expf(q * a - m1[v]) * rd1[v];
            }
            gqs[t] = acc;
        }
        __syncthreads();
        if (t < 256) {
            for (int rr = 0; rr < 8; rr++) {
                int r = w * 8 + rr;
                float z[8], mx = -1e30f;
                #pragma unroll
                for (int j = 0; j < 8; j++) {
                    int e = lane + j * 32;
                    z[j] = gqs[e] * g_k[r * 256 + e] * beta[e] * scale;
                    mx = fmaxf(mx, z[j]);
                }
                mx = warp_max(mx);
                float s = 0.f;
                #pragma unroll
                for (int j = 0; j < 8; j++) s += expf(z[j] - mx);
                s = warp_sum(s);
                if (lane == 0) { m2[r] = mx; rd2[r] = 1.f / s; }
            }
        }
        __syncthreads();
        if (t < 256) {
            float bsc = beta[t] * scale, gq_e = gqs[t], acc = 0.f;
            for (int v = 0; v < 64; v++) {
                float p = gq_e * g_k[v * 256 + t];
                acc += p * expf(p * bsc - m2[v]) * rd2[v];
            }
            g_gk[t] = acc;
        }
        return;
    }

    int r = bid;
    int ne = g_elln[0][r], nd = g_elln[1][r];
    for (int i = t; i < ne; i += 512) { ve[i] = g_ellval[0][r * RCAP + i]; ce[i] = g_ellcol[0][r * RCAP + i]; }
    for (int i = t; i < nd; i += 512) { vd[i] = g_ellval[1][r * RCAP + i]; cd[i] = g_ellcol[1][r * RCAP + i]; }
    __syncthreads();

    int tt = t & 255;
    int eg = (tt & 63) << 2, seg = tt >> 6;
    int half = t >> 8;                      // 0: ehr, 1: ddi (concurrent)
    const float* vals = half ? vd : ve;
    const int*   cols = half ? cd : ce;
    const float* tsrc = half ? g_t[1] : g_t[0];
    int n = half ? nd : ne;

    float4 acc = {0.f, 0.f, 0.f, 0.f};
    for (int i = (n * seg) >> 2; i < (n * (seg + 1)) >> 2; i++) {
        float vv = vals[i];
        const float4 tv = *(const float4*)(tsrc + (size_t)cols[i] * 256 + eg);
        acc.x += vv * tv.x; acc.y += vv * tv.y; acc.z += vv * tv.z; acc.w += vv * tv.w;
    }
    part[t] = acc;
    __syncthreads();
    if (t < 64) {
        int eg2 = t << 2;
        float4 e0 = part[t], e1 = part[t + 64], e2 = part[t + 128], e3 = part[t + 192];
        float4 d0 = part[t + 256], d1 = part[t + 320], d2 = part[t + 384], d3 = part[t + 448];
        float iv = inter[0];
        float4 be = *(const float4*)(b2e + eg2);
        float4 bd = *(const float4*)(b2d + eg2);
        float4 o;
        o.x = (e0.x + e1.x + e2.x + e3.x + be.x) - iv * (d0.x + d1.x + d2.x + d3.x + bd.x);
        o.y = (e0.y + e1.y + e2.y + e3.y + be.y) - iv * (d0.y + d1.y + d2.y + d3.y + bd.y);
        o.z = (e0.z + e1.z + e2.z + e3.z + be.z) - iv * (d0.z + d1.z + d2.z + d3.z + bd.z);
        o.w = (e0.w + e1.w + e2.w + e3.w + be.w) - iv * (d0.w + d1.w + d2.w + d3.w + bd.w);
        *(float4*)(&g_dm[(size_t)r * 256 + eg2]) = o;
    }
}

// ============================================================================
// L4: feat rows + visit score, 1024 threads (e-split 4-way)   (64 blocks)
// ============================================================================
__global__ void __launch_bounds__(1024) k4_feat(const float* __restrict__ wr) {
    __shared__ float gvr[256], gv63[256];
    __shared__ float pf[4][256], p63[4][256];
    __shared__ float red[8];
    int v = blockIdx.x, t = threadIdx.x;
    int col = t & 255, seg = t >> 8;
    if (t < 256) {
        float gk = g_gk[t];
        gvr[t]  = gk * g_v[v * 256 + t];
        gv63[t] = gk * g_v[63 * 256 + t];
    }
    __syncthreads();
    float a = 0.f, b = 0.f;
    int e0 = seg * 64;
    #pragma unroll 8
    for (int e = e0; e < e0 + 64; e++) {
        float wv = wr[e * 256 + col];
        a += gvr[e] * wv;
        b += gv63[e] * wv;
    }
    pf[seg][col] = a; p63[seg][col] = b;
    __syncthreads();
    if (t < 256) {
        float fr  = g_q[v * 256 + t]  + ((pf[0][t] + pf[1][t]) + (pf[2][t] + pf[3][t]));
        float f63 = g_q[63 * 256 + t] + ((p63[0][t] + p63[1][t]) + (p63[2][t] + p63[3][t]));
        if (v == 63) g_query[t] = fr;
        float p = warp_sum(fr * f63);
        if ((t & 31) == 0) red[t >> 5] = p;
    }
    __syncthreads();
    if (t == 0 && v < 63) {
        float s = 0.f;
        #pragma unroll
        for (int i = 0; i < 8; i++) s += red[i];
        g_vs[v] = s;
    }
}

// ============================================================================
// L5: fact1 partials [blocks 0..124] + fact2 per-visit partials [125..187]
// ============================================================================
__global__ void __launch_bounds__(256) k5_fact(const int* __restrict__ med) {
    int t = threadIdx.x, lane = t & 31, w = t >> 5, bid = blockIdx.x;

    if (bid < 125) {
        __shared__ float qys[256], sc[32], evs[32];
        int r0 = bid * 32;
        qys[t] = g_query[t];
        __syncthreads();
        const float4* qp = (const float4*)qys;
        #pragma unroll
        for (int jr = 0; jr < 4; jr++) {
            int j = w * 4 + jr;
            const float4* dp = (const float4*)(g_dm + (size_t)(r0 + j) * 256);
            float4 d0 = dp[lane], q0 = qp[lane];
            float4 d1 = dp[lane + 32], q1 = qp[lane + 32];
            float a = d0.x * q0.x + d0.y * q0.y + d0.z * q0.z + d0.w * q0.w
                    + d1.x * q1.x + d1.y * q1.y + d1.z * q1.z + d1.w * q1.w;
            a = warp_sum(a);
            if (lane == 0) sc[j] = a;
        }
        __syncthreads();
        if (t < 32) {
            float s0 = sc[t];
            float m = warp_max(s0);
            float e = expf(s0 - m);
            evs[t] = e;
            float s = warp_sum(e);
            if (t == 0) { g_m[bid] = m; g_esum[bid] = s; }
        }
        __syncthreads();
        float acc = 0.f;
        #pragma unroll 4
        for (int j = 0; j < 32; j++) acc += evs[j] * g_dm[(size_t)(r0 + j) * 256 + t];
        g_f1p[bid][t] = acc;
    } else {
        // fact2 for visit i: g_f2p[i] = exp(vs_i - vmax) * sum_{k unique} dm[code_ik]
        int i = bid - 125;
        __shared__ float vsv[64];
        __shared__ int cds[16];
        __shared__ unsigned mk;
        __shared__ float vmx;
        if (t < 63) vsv[t] = g_vs[t];
        if (t >= 64 && t < 80) cds[t - 64] = med[i * 16 + (t - 64)];
        __syncthreads();
        if (t == 0) {
            float m = -1e30f;
            for (int j = 0; j < 63; j++) m = fmaxf(m, vsv[j]);
            vmx = m;
            unsigned mm = 0;
            for (int k = 0; k < 16; k++) {
                int c = cds[k];
                bool dup = false;
                for (int j = 0; j < k; j++) dup |= (cds[j] == c);
                if (!dup) mm |= (1u << k);
            }
            mk = mm;
        }
        __syncthreads();
        float wv = expf(vsv[i] - vmx);
        unsigned m = mk;
        float acc = 0.f;
        #pragma unroll 4
        for (int k = 0; k < 16; k++)
            if ((m >> k) & 1u) acc += g_dm[(size_t)cds[k] * 256 + t];
        g_f2p[i][t] = wv * acc;
    }
}

// ============================================================================
// L6: assemble h, hidden = relu(h@w1+b1)    (16 blocks x 512, 32 outputs each)
// ============================================================================
__global__ void __launch_bounds__(512) k6_hidden(
    const float* __restrict__ w1, const float* __restrict__ b1) {
    __shared__ float h[768];
    __shared__ float sA[125], sB[125], vsv[63];
    __shared__ float part[512];
    __shared__ float gM_s, gden_s, vmax_s, vsuminv_s;
    int t = threadIdx.x;

    if (t < 125) { sA[t] = g_m[t]; sB[t] = g_esum[t]; }
    if (t >= 128 && t < 191) vsv[t - 128] = g_vs[t - 128];
    __syncthreads();
    if (t == 0) { float M = -1e30f; for (int b = 0; b < 125; b++) M = fmaxf(M, sA[b]); gM_s = M; }
    if (t == 1) { float m = -1e30f; for (int i = 0; i < 63; i++) m = fmaxf(m, vsv[i]); vmax_s = m; }
    __syncthreads();
    if (t < 125) sA[t] = expf(sA[t] - gM_s);
    __syncthreads();
    if (t == 0) { float s = 0.f; for (int b = 0; b < 125; b++) s += sA[b] * sB[b]; gden_s = 1.f / s; }
    if (t == 1) { float s = 0.f; for (int i = 0; i < 63; i++) s += expf(vsv[i] - vmax_s); vsuminv_s = 1.f / s; }
    __syncthreads();
    if (t < 256) {
        h[t] = g_query[t];
        float a = 0.f;
        for (int b = 0; b < 125; b++) a += sA[b] * g_f1p[b][t];
        h[256 + t] = a * gden_s;
        float f2 = 0.f;
        for (int i = 0; i < 63; i++) f2 += g_f2p[i][t];
        h[512 + t] = f2 * vsuminv_s;
    }
    __syncthreads();
    int o = blockIdx.x * 32 + (t & 31);
    int js = t >> 5;                        // 16 segments of 48 j's
    float acc = 0.f;
    int j0 = js * 48;
    #pragma unroll 8
    for (int j = j0; j < j0 + 48; j++) acc += h[j] * w1[(size_t)j * 512 + o];
    part[t] = acc;
    __syncthreads();
    if (t < 32) {
        float s = b1[o];
        #pragma unroll
        for (int m = 0; m < 16; m++) s += part[m * 32 + t];
        g_hid[o] = fmaxf(s, 0.f);
    }
}

// ============================================================================
// L7: output layer + sigmoid   (63 blocks x 512, o-split 8-way)
// ============================================================================
__global__ void __launch_bounds__(512) k7_out(
    const float* __restrict__ w2, const float* __restrict__ b2,
    float* __restrict__ out) {
    __shared__ float hid[512];
    __shared__ float part[512];
    int t = threadIdx.x;
    hid[t] = g_hid[t];
    __syncthreads();
    int tc = t & 63, os = t >> 6;
    int c = blockIdx.x * 64 + tc;
    float acc = 0.f;
    if (c < 4000) {
        int o0 = os * 64;
        #pragma unroll 8
        for (int o = o0; o < o0 + 64; o++) acc += hid[o] * w2[(size_t)o * 4000 + c];
    }
    part[t] = acc;
    __syncthreads();
    if (os == 0 && c < 4000) {
        float r = b2[c];
        #pragma unroll
        for (int m = 0; m < 8; m++) r += part[m * 64 + tc];
        out[c] = r;
        g_sp[c] = 1.f / (1.f + expf(-r));
    }
}

// ============================================================================
// L8: batch_neg from ddi ELL pattern (off-diag) + raw diagonal  (32 blocks)
//     fused final reduction via atomic counter (deterministic fixed order)
// ============================================================================
__global__ void __launch_bounds__(128) k8_neg(
    const float* __restrict__ raw, float* __restrict__ out, int out_size) {
    __shared__ float sp[VMED];
    __shared__ float wred[4];
    int t = threadIdx.x, bid = blockIdx.x;
    for (int i = t; i < VMED; i += 128) sp[i] = g_sp[i];
    __syncthreads();
    float acc = 0.f;
    int r = bid * 125 + t;
    if (t < 125) {
        int n = g_elln[1][r];
        const int* cols = &g_ellcol[1][r * RCAP];
        float s = 0.f;
        for (int i = 0; i < n; i++) {
            int c = cols[i];
            if (c != r) s += sp[c];
        }
        s += raw[(size_t)r * 4000 + r] * sp[r];   // diagonal of raw directly
        acc = s * sp[r];
    }
    float ws = warp_sum(acc);
    if ((t & 31) == 0) wred[t >> 5] = ws;
    __syncthreads();
    if (t == 0) {
        g_negp[bid] = (wred[0] + wred[1]) + (wred[2] + wred[3]);
        __threadfence();
        int old = atomicAdd(&g_ctr, 1);
        if (old == 31) {
            float s = 0.f;
            volatile float* np = g_negp;
            for (int b = 0; b < 32; b++) s += np[b];
            if (out_size > 4000) out[4000] = 0.0005f * s;
            g_ctr = 0;
        }
    }
}

// ---------------------------------------------------------------------------
extern "C" void kernel_launch(void* const* d_in, const int* in_sizes, int n_in,
                              void* d_out, int out_size) {
    const int*   proc    = (const int*)d_in[0];
    const int*   med     = (const int*)d_in[1];
    const float* emb     = (const float*)d_in[2];
    const float* conv_w  = (const float*)d_in[3];
    const float* conv_b  = (const float*)d_in[4];
    const float* wq      = (const float*)d_in[5];
    const float* wk      = (const float*)d_in[6];
    const float* wv      = (const float*)d_in[7];
    const float* wr      = (const float*)d_in[8];
    const float* alpha   = (const float*)d_in[9];
    const float* beta    = (const float*)d_in[10];
    const float* ehr_adj = (const float*)d_in[11];
    const float* ddi_adj = (const float*)d_in[12];
    const float* ddi_raw = (const float*)d_in[13];
    const float* ehr_w1  = (const float*)d_in[14];
    const float* ehr_b1  = (const float*)d_in[15];
    const float* ehr_w2  = (const float*)d_in[16];
    const float* ehr_b2  = (const float*)d_in[17];
    const float* ddi_w1  = (const float*)d_in[18];
    const float* ddi_b1  = (const float*)d_in[19];
    const float* ddi_w2  = (const float*)d_in[20];
    const float* ddi_b2  = (const float*)d_in[21];
    const float* inter   = (const float*)d_in[22];
    const float* out_w1  = (const float*)d_in[23];
    const float* out_b1  = (const float*)d_in[24];
    const float* out_w2  = (const float*)d_in[25];
    const float* out_b2  = (const float*)d_in[26];
    float* out = (float*)d_out;

    k1_scan_front<<<2 * VMED + 64, 256>>>(ehr_adj, ddi_adj, ehr_w1, ehr_b1,
                                          ddi_w1, ddi_b1, proc, emb, conv_w, conv_b);
    k2_gemm_qkv<<<692, 256>>>(ehr_w2, ddi_w2, wq, wk, wv);
    k3_gcn2_ff<<<VMED + 1, 512>>>(ehr_b2, ddi_b2, inter, alpha, beta);
    k4_feat<<<64, 1024>>>(wr);
    k5_fact<<<188, 256>>>(med);
    k6_hidden<<<16, 512>>>(out_w1, out_b1);
    k7_out<<<63, 512>>>(out_w2, out_b2, out);
    k8_neg<<<32, 128>>>(ddi_raw, out, out_size);
}